// round 16
// baseline (speedup 1.0000x reference)
#include <cuda_runtime.h>

// MatchAttention fused forward, fixed shape:
// B=2, H=W=64, N=4096, C=256, heads=8, Ch=32, r=3 -> K=49, scale=1, l1_norm.
#define HH   64
#define WW   64
#define CC   256
#define NHD  8
#define CH   32
#define RR   3
#define KWIN 49
#define NPIX (HH * WW)

// R16: one warp = one pixel x 2 heads (16 lanes/head, 2 channels/lane).
// Every gather is a float2 LDG.64 whose 16-lane halves each cover one
// 128-byte row exactly -> 2 cache lines per LDG instead of 4, halving the
// within-LDG wavefront replay serialization (2.07 cyc blocking per extra
// line) that the cost model identifies as the binding resource.
// Transposed butterfly now has a 4th (xor 8) round; pair lanes {t, t+8}
// hold the same slot so the denominator reduce still needs only xor 1,2,4.
// Streaming softmax with fixed reference (sim <= 0 always; d ~ 36+/-5 so
// exp(-d) is far above fp32 underflow); final 1/sum rescale == reference.
__global__ __launch_bounds__(256, 4)
void match_attn_kernel(const float* __restrict__ moff,   // [B,N,h,2]
                       const float* __restrict__ qp,     // [B,N,C]
                       const float* __restrict__ kp,     // [B,N,C]
                       const float* __restrict__ vp,     // [B,N,C]
                       float* __restrict__ out,          // [B,N,C]
                       float* __restrict__ attn_out)     // [B,N,h,K]
{
    const int warpGlobal = (blockIdx.x * blockDim.x + threadIdx.x) >> 5;
    const int lane = threadIdx.x & 31;
    const int lih  = lane & 15;   // lane within 16-lane head half
    const int half = lane >> 4;   // 0 or 1

    const int p   = warpGlobal >> 2;          // global pixel (incl batch)
    const int wip = warpGlobal & 3;           // warp-in-pixel
    const int g   = wip + half * 4;           // head: this warp = {wip, wip+4}

    const int n    = p & (NPIX - 1);
    const int base = p - n;                   // b*N
    const int y    = n / WW;
    const int x    = n & (WW - 1);

    // rounded per-head window center (rintf == jnp.round, half-to-even)
    const float2 off2 = *(const float2*)&moff[(size_t)(p * NHD + g) * 2];
    const int cy = y + (int)rintf(off2.x);
    const int cx = x + (int)rintf(off2.y);

    const int chBase = g * CH + lih * 2;      // 2 channels per lane

    // clamped row/col element-offsets; chBase folded into the row term
    int pyW[7], pxc[7];
#pragma unroll
    for (int i = 0; i < 7; i++) {
        const int py = min(max(cy + i - RR, 0), HH - 1);
        const int px = min(max(cx + i - RR, 0), WW - 1);
        pyW[i] = (base + py * WW) * CC + chBase;
        pxc[i] = px * CC;
    }

    const float2 q2 = *(const float2*)(qp + (size_t)p * CC + chBase);

    const bool b0 = (lih & 1) != 0;
    const bool b1 = (lih & 2) != 0;
    const bool b2 = (lih & 4) != 0;
    const int  hbase = lane & 16;   // first lane of this 16-lane half

    float w_own[6];
    float s = 0.f;
    float2 acc = make_float2(0.f, 0.f);

#pragma unroll
    for (int j = 0; j < 6; j++) {
        // ---- 8 k-gathers (LDG.64, 2 lines each) + partial L1 distances ------
        float pd[8];
#pragma unroll
        for (int t = 0; t < 8; t++) {
            const int kk = j * 8 + t;
            const float2 k2 = *(const float2*)(kp + pyW[kk / 7] + pxc[kk % 7]);
            pd[t] = fabsf(q2.x - k2.x) + fabsf(q2.y - k2.y);
        }

        // ---- transposed butterfly over the 16-lane half ----------------------
        // 3 rounds (xor 1,2,4): subgroup {0-7} and {8-15} each end with their
        // partial of slot 8j+(lih&7); round 4 (xor 8) merges the two partials.
        float r4[4];
#pragma unroll
        for (int t = 0; t < 4; t++) {
            const float keep = b0 ? pd[2 * t + 1] : pd[2 * t];
            const float send = b0 ? pd[2 * t]     : pd[2 * t + 1];
            r4[t] = keep + __shfl_xor_sync(0xffffffffu, send, 1);
        }
        float r2[2];
#pragma unroll
        for (int t = 0; t < 2; t++) {
            const float keep = b1 ? r4[2 * t + 1] : r4[2 * t];
            const float send = b1 ? r4[2 * t]     : r4[2 * t + 1];
            r2[t] = keep + __shfl_xor_sync(0xffffffffu, send, 2);
        }
        const float keep = b2 ? r2[1] : r2[0];
        const float send = b2 ? r2[0] : r2[1];
        const float dpart = keep + __shfl_xor_sync(0xffffffffu, send, 4);
        const float d = dpart + __shfl_xor_sync(0xffffffffu, dpart, 8);

        const float w = __expf(-d);   // slot 8j+(lih&7), duplicated on lane pair
        s += w;                       // per-lane column sum (pairs identical)
        w_own[j] = w;

        // ---- v accumulation (LDG.64): broadcast w from slot's owner lane ----
#pragma unroll
        for (int t = 0; t < 8; t++) {
            const int kk = j * 8 + t;
            const float wt = __shfl_sync(0xffffffffu, w, hbase | t);
            const float2 v2 = *(const float2*)(vp + pyW[kk / 7] + pxc[kk % 7]);
            acc.x = fmaf(wt, v2.x, acc.x);
            acc.y = fmaf(wt, v2.y, acc.y);
        }
    }

    // ---- remainder slot 48 (row 6, col 6) ------------------------------------
    float w48;
    {
        const int off48 = pyW[6] + pxc[6];
        const float2 k2 = *(const float2*)(kp + off48);
        float d = fabsf(q2.x - k2.x) + fabsf(q2.y - k2.y);
        d += __shfl_xor_sync(0xffffffffu, d, 1);
        d += __shfl_xor_sync(0xffffffffu, d, 2);
        d += __shfl_xor_sync(0xffffffffu, d, 4);
        d += __shfl_xor_sync(0xffffffffu, d, 8);
        w48 = __expf(-d);                        // full weight on all 16 lanes
        const float2 v2 = *(const float2*)(vp + off48);
        acc.x = fmaf(w48, v2.x, acc.x);
        acc.y = fmaf(w48, v2.y, acc.y);
    }

    // ---- normalization --------------------------------------------------------
    // s on lane lih covers slot-column lih&7; subgroups {0-7} and {8-15} hold
    // identical copies, so xor 1,2,4 gives the full head sum. Then add slot 48.
    s += __shfl_xor_sync(0xffffffffu, s, 1);
    s += __shfl_xor_sync(0xffffffffu, s, 2);
    s += __shfl_xor_sync(0xffffffffu, s, 4);
    s += w48;
    const float inv = 1.f / s;

    float* aout = attn_out + (size_t)(p * NHD + g) * KWIN;
    if (lih < 8) {
#pragma unroll
        for (int j = 0; j < 6; j++) aout[j * 8 + lih] = w_own[j] * inv;
        if (lih == 0) aout[48] = w48 * inv;
    }

    acc.x *= inv; acc.y *= inv;
    *(float2*)(out + (size_t)p * CC + chBase) = acc;
}

extern "C" void kernel_launch(void* const* d_in, const int* in_sizes, int n_in,
                              void* d_out, int out_size) {
    const float* moff = (const float*)d_in[0];   // [B,N,h,2]
    const float* q    = (const float*)d_in[1];   // [B,N,C]
    const float* k    = (const float*)d_in[2];
    const float* v    = (const float*)d_in[3];

    float* out = (float*)d_out;                  // output [B,N,C] first...
    const int qElems = in_sizes[1];              // B*N*C
    float* attn_out = out + qElems;              // ...then attn_out [B,N,h,K]

    const int items = in_sizes[0] / 2;           // B*N*h
    const int totalWarps = items / 2;            // 2 heads per warp
    const int threads = 256;
    const int blocks = (totalWarps * 32) / threads;   // 4096

    match_attn_kernel<<<blocks, threads>>>(moff, q, k, v, out, attn_out);
}